// round 14
// baseline (speedup 1.0000x reference)
#include <cuda_runtime.h>
#include <cuda_bf16.h>
#include <cstdint>
#include <cstddef>

constexpr int T=256, Bsz=64, D=1024, H=1024, R=256;
constexpr int G4H=4*H, TB=T*Bsz, NB=128, NTH=512;

// static scratch (allocation-free)
__device__ __align__(256) __nv_bfloat16 g_Xp[(size_t)TB*3*D];    // X'  [TB, 3072]
__device__ __align__(256) __nv_bfloat16 g_Wp[(size_t)G4H*3*R];   // Wx' [4096, 768]
__device__ __align__(256) __nv_bfloat16 g_Up[(size_t)R*3*D];     // UxT'[256, 3072]
__device__ __align__(256) __nv_bfloat16 g_Pp[(size_t)TB*3*R];    // P'  [TB, 768]
__device__ __align__(256) __nv_bfloat16 g_Whp[(size_t)G4H*3*R];  // Wh' [4096, 768]
__device__ __align__(256) float g_pf[Bsz*R];                     // p fp32 per step
__device__ float g_Gx[(size_t)TB*G4H];
__device__ float g_d2x[G4H];
__device__ float g_d2h[G4H];
__device__ float g_h[Bsz*H];
__device__ __align__(128) unsigned g_flags[NB*8];                // 32B-strided flag board

// ---------------- helpers ----------------
__device__ __forceinline__ void fma2(unsigned long long& acc,
                                     unsigned long long a, unsigned long long b) {
    asm("fma.rn.f32x2 %0, %1, %2, %0;" : "+l"(acc) : "l"(a), "l"(b));
}
__device__ __forceinline__ float2 unpack2(unsigned long long v) {
    float2 f; asm("mov.b64 {%0, %1}, %2;" : "=f"(f.x), "=f"(f.y) : "l"(v)); return f;
}
__device__ __forceinline__ uint32_t smem_u32(const void* p) {
    uint32_t a;
    asm("{ .reg .u64 t; cvta.to.shared.u64 t, %1; cvt.u32.u64 %0, t; }" : "=r"(a) : "l"(p));
    return a;
}
__device__ __forceinline__ void cp16(uint32_t dst, const void* src) {
    asm volatile("cp.async.cg.shared.global [%0], [%1], 16;" :: "r"(dst), "l"(src) : "memory");
}
__device__ __forceinline__ uint32_t swz(uint32_t o) { return o ^ ((o >> 3) & 0x70); }

__device__ __forceinline__ void ldsm4(uint32_t* r, uint32_t addr) {
    asm volatile("ldmatrix.sync.aligned.m8n8.x4.shared.b16 {%0,%1,%2,%3}, [%4];"
        : "=r"(r[0]), "=r"(r[1]), "=r"(r[2]), "=r"(r[3]) : "r"(addr));
}
__device__ __forceinline__ void mma16816(float* c, const uint32_t* a,
                                         uint32_t b0, uint32_t b1) {
    asm volatile(
        "mma.sync.aligned.m16n8k16.row.col.f32.bf16.bf16.f32 "
        "{%0,%1,%2,%3}, {%4,%5,%6,%7}, {%8,%9}, {%0,%1,%2,%3};"
        : "+f"(c[0]), "+f"(c[1]), "+f"(c[2]), "+f"(c[3])
        : "r"(a[0]), "r"(a[1]), "r"(a[2]), "r"(a[3]), "r"(b0), "r"(b1));
}

// ---------------- grid barrier: distributed flag board ----------------
// Arrival: tid0 st.release.gpu flags[myCTA] = target  (plain store, no atomic).
// Detect:  threads 0..NB-1 each acquire-poll one producer's flag (parallel, MLP=NB).
// HB: producer stores -> its release-store -> consumer's acquire-load -> bar.sync.
__device__ __forceinline__ void gbar(unsigned target) {
    __syncthreads();
    if (threadIdx.x == 0)
        asm volatile("st.release.gpu.global.u32 [%0], %1;"
                     :: "l"(&g_flags[blockIdx.x*8]), "r"(target) : "memory");
    if (threadIdx.x < NB) {
        unsigned v;
        do {
            asm volatile("ld.acquire.gpu.global.u32 %0, [%1];"
                         : "=r"(v) : "l"(&g_flags[threadIdx.x*8]) : "memory");
        } while (v < target);
    }
    __syncthreads();
}

// ---------------- conversions ----------------
__global__ void conv_pack(const float* __restrict__ s, __nv_bfloat16* __restrict__ d,
                          int ls, int n4)
{
    const int rl = 1 << ls, mask = rl - 1;
    for (int i = blockIdx.x*blockDim.x + threadIdx.x; i < n4; i += gridDim.x*blockDim.x) {
        float4 v = reinterpret_cast<const float4*>(s)[i];
        int e = i * 4, m = e >> ls, col = e & mask;
        __nv_bfloat16 h0=__float2bfloat16(v.x), h1=__float2bfloat16(v.y);
        __nv_bfloat16 h2=__float2bfloat16(v.z), h3=__float2bfloat16(v.w);
        __nv_bfloat162 ha{h0,h1}, hb{h2,h3};
        __nv_bfloat162 la{__float2bfloat16(v.x-__bfloat162float(h0)),
                          __float2bfloat16(v.y-__bfloat162float(h1))};
        __nv_bfloat162 lb{__float2bfloat16(v.z-__bfloat162float(h2)),
                          __float2bfloat16(v.w-__bfloat162float(h3))};
        __nv_bfloat16* rp = d + (size_t)m*3*rl + col;
        reinterpret_cast<__nv_bfloat162*>(rp)[0]        = ha;
        reinterpret_cast<__nv_bfloat162*>(rp)[1]        = hb;
        reinterpret_cast<__nv_bfloat162*>(rp + rl)[0]   = la;
        reinterpret_cast<__nv_bfloat162*>(rp + rl)[1]   = lb;
        reinterpret_cast<__nv_bfloat162*>(rp + 2*rl)[0] = ha;
        reinterpret_cast<__nv_bfloat162*>(rp + 2*rl)[1] = hb;
    }
}
__global__ void conv_uT(const float* __restrict__ u, __nv_bfloat16* __restrict__ d)
{
    for (int i = blockIdx.x*blockDim.x + threadIdx.x; i < R*D; i += gridDim.x*blockDim.x) {
        int n = i >> 10, dd = i & 1023;
        float v = u[(size_t)dd*R + n];
        __nv_bfloat16 h = __float2bfloat16(v);
        __nv_bfloat16 l = __float2bfloat16(v - __bfloat162float(h));
        d[(size_t)n*3*D + dd]       = h;
        d[(size_t)n*3*D + D + dd]   = h;
        d[(size_t)n*3*D + 2*D + dd] = l;
    }
}
// rows of 256 fp32 -> rows of 768 bf16 [hi | hi | lo]
__global__ void conv_wB(const float* __restrict__ w, __nv_bfloat16* __restrict__ d)
{
    for (int i = blockIdx.x*blockDim.x + threadIdx.x; i < G4H*R/4; i += gridDim.x*blockDim.x) {
        float4 v = reinterpret_cast<const float4*>(w)[i];
        int e = i * 4, m = e >> 8, col = e & 255;
        __nv_bfloat16 h0=__float2bfloat16(v.x), h1=__float2bfloat16(v.y);
        __nv_bfloat16 h2=__float2bfloat16(v.z), h3=__float2bfloat16(v.w);
        __nv_bfloat162 ha{h0,h1}, hb{h2,h3};
        __nv_bfloat162 la{__float2bfloat16(v.x-__bfloat162float(h0)),
                          __float2bfloat16(v.y-__bfloat162float(h1))};
        __nv_bfloat162 lb{__float2bfloat16(v.z-__bfloat162float(h2)),
                          __float2bfloat16(v.w-__bfloat162float(h3))};
        __nv_bfloat16* rp = d + (size_t)m*3*R + col;
        reinterpret_cast<__nv_bfloat162*>(rp)[0]         = ha;
        reinterpret_cast<__nv_bfloat162*>(rp)[1]         = hb;
        reinterpret_cast<__nv_bfloat162*>(rp + R)[0]     = ha;
        reinterpret_cast<__nv_bfloat162*>(rp + R)[1]     = hb;
        reinterpret_cast<__nv_bfloat162*>(rp + 2*R)[0]   = la;
        reinterpret_cast<__nv_bfloat162*>(rp + 2*R)[1]   = lb;
    }
}

// ---------------- prep ----------------
__global__ void prep_kernel(const float* __restrict__ u_x, const float* __restrict__ w_x,
                            const float* __restrict__ dia_x,
                            const float* __restrict__ u_h, const float* __restrict__ w_h,
                            const float* __restrict__ dia_h, const float* __restrict__ h0)
{
    int n = blockIdx.x*blockDim.x + threadIdx.x;   // 0..8191
    if (n < NB*8) g_flags[n] = 0u;                 // flag-board reset (replay-safe)
    const float *u, *w, *dia; float* o; int idx;
    if (n < G4H) { u=u_x; w=w_x; dia=dia_x; o=g_d2x; idx=n; }
    else         { u=u_h; w=w_h; dia=dia_h; o=g_d2h; idx=n-G4H; }
    int d = idx & (H-1);
    const float4* ur = reinterpret_cast<const float4*>(u + (size_t)d*R);
    const float4* wr = reinterpret_cast<const float4*>(w + (size_t)idx*R);
    float s = 0.f;
    #pragma unroll 8
    for (int k = 0; k < R/4; ++k) {
        float4 a = ur[k], b = wr[k];
        s += a.x*b.x + a.y*b.y + a.z*b.z + a.w*b.w;
    }
    o[idx] = dia[d] - s;
    for (int i = n; i < Bsz*H; i += 8192) g_h[i] = h0[i];
}

// ---------------------------------------------------------------------------
// HMMA GEMM for precompute (unchanged)
// ---------------------------------------------------------------------------
constexpr size_t GSM = 2*32768 + 1024;

template<int EPI>
__global__ void __launch_bounds__(256, 1) gemm_mma(
    const __nv_bfloat16* __restrict__ Ap, const __nv_bfloat16* __restrict__ Bp,
    int K, int Nld, float* __restrict__ Cf, __nv_bfloat16* __restrict__ Pp,
    const float* __restrict__ X, const float* __restrict__ d2v,
    const float* __restrict__ bias)
{
    extern __shared__ char smraw[];
    const uint32_t sb = (smem_u32(smraw) + 1023) & ~1023u;
    const int tid = threadIdx.x, lane = tid & 31, wid = tid >> 5;
    const int wm = wid >> 2, wn = wid & 3;
    const int m0 = blockIdx.y * 128, n0 = blockIdx.x * 128;

    const __nv_bfloat16* Asrc = Ap + (size_t)m0 * K;
    const __nv_bfloat16* Bsrc = Bp + (size_t)n0 * K;
    const int lrow = tid >> 3, lc8 = tid & 7;

    auto load_stage = [&](int kc, int s) {
        uint32_t base = sb + s * 32768;
        #pragma unroll
        for (int rr = 0; rr < 4; ++rr) {
            int row = lrow + rr * 32;
            cp16(base + swz(row*128 + lc8*16),
                 Asrc + (size_t)row*K + kc + lc8*8);
            cp16(base + 16384 + swz(row*128 + lc8*16),
                 Bsrc + (size_t)row*K + kc + lc8*8);
        }
        asm volatile("cp.async.commit_group;" ::: "memory");
    };

    float acc[4][4][4];
    #pragma unroll
    for (int a = 0; a < 4; ++a)
        #pragma unroll
        for (int b = 0; b < 4; ++b)
            #pragma unroll
            for (int c = 0; c < 4; ++c) acc[a][b][c] = 0.f;

    const int nIter = K / 64;
    load_stage(0, 0);
    for (int it = 0; it < nIter; ++it) {
        if (it + 1 < nIter) {
            load_stage((it + 1) * 64, (it + 1) & 1);
            asm volatile("cp.async.wait_group 1;" ::: "memory");
        } else {
            asm volatile("cp.async.wait_group 0;" ::: "memory");
        }
        __syncthreads();
        const uint32_t aB = sb + (it & 1) * 32768;
        const uint32_t bB = aB + 16384;
        #pragma unroll
        for (int kk = 0; kk < 4; ++kk) {
            uint32_t afr[4][4];
            #pragma unroll
            for (int mi = 0; mi < 4; ++mi) {
                int rowa = wm*64 + mi*16 + (lane & 15);
                ldsm4(afr[mi], aB + swz(rowa*128 + kk*32 + (lane >> 4)*16));
            }
            uint32_t bfr[2][4];
            #pragma unroll
            for (int nb = 0; nb < 2; ++nb) {
                int sub = lane >> 3;
                int rn = wn*32 + nb*16 + (sub >> 1)*8 + (lane & 7);
                ldsm4(bfr[nb], bB + swz(rn*128 + kk*32 + (sub & 1)*16));
            }
            #pragma unroll
            for (int mi = 0; mi < 4; ++mi)
                #pragma unroll
                for (int nb = 0; nb < 2; ++nb) {
                    mma16816(acc[mi][nb*2],     afr[mi], bfr[nb][0], bfr[nb][1]);
                    mma16816(acc[mi][nb*2 + 1], afr[mi], bfr[nb][2], bfr[nb][3]);
                }
        }
        __syncthreads();
    }

    const int quad = lane >> 2, tx2 = (lane & 3) * 2;
    #pragma unroll
    for (int mi = 0; mi < 4; ++mi) {
        #pragma unroll
        for (int n8 = 0; n8 < 4; ++n8) {
            int n = n0 + wn*32 + n8*8 + tx2;
            #pragma unroll
            for (int half = 0; half < 2; ++half) {
                int m = m0 + wm*64 + mi*16 + quad + half*8;
                float v0 = acc[mi][n8][half*2], v1 = acc[mi][n8][half*2 + 1];
                if constexpr (EPI == 2) {
                    float x0 = X[(size_t)m*H + (n & (H-1))];
                    float x1 = X[(size_t)m*H + ((n+1) & (H-1))];
                    v0 += x0*d2v[n]   + bias[n];
                    v1 += x1*d2v[n+1] + bias[n+1];
                    *reinterpret_cast<float2*>(&Cf[(size_t)m*Nld + n]) =
                        make_float2(v0, v1);
                } else {
                    __nv_bfloat16 h0 = __float2bfloat16(v0);
                    __nv_bfloat16 h1 = __float2bfloat16(v1);
                    __nv_bfloat162 hh{h0, h1};
                    __nv_bfloat162 ll{__float2bfloat16(v0 - __bfloat162float(h0)),
                                      __float2bfloat16(v1 - __bfloat162float(h1))};
                    __nv_bfloat16* rp = Pp + (size_t)m*(3*R) + n;
                    *reinterpret_cast<__nv_bfloat162*>(rp)         = hh;
                    *reinterpret_cast<__nv_bfloat162*>(rp + R)     = ll;
                    *reinterpret_cast<__nv_bfloat162*>(rp + 2*R)   = hh;
                }
            }
        }
    }
}

// ---------------------------------------------------------------------------
// persistent recurrent kernel (identical to R13 except gbar)
// ---------------------------------------------------------------------------
constexpr int OFF_W   = 65792;
constexpr int OFF_STG = 115456;
constexpr int SMEM_REC = 182016;
constexpr int WST  = 1552;
constexpr int AST  = 1040;

__global__ void __launch_bounds__(NTH, 1) lstm_rec(
    const float* __restrict__ c0, const float* __restrict__ h0,
    const float* __restrict__ u_h,
    const float* __restrict__ b_h, float* __restrict__ out, int full_out)
{
    extern __shared__ char smc[];
    float* su  = reinterpret_cast<float*>(smc);
    float* hst = reinterpret_cast<float*>(smc + OFF_STG);
    float* sp  = reinterpret_cast<float*>(smc + OFF_STG);
    const uint32_t sb = smem_u32(smc);
    const uint32_t WB = sb + OFF_W, SB = sb + OFF_STG;

    const int tid = threadIdx.x, bk = blockIdx.x;
    const int rb = bk & 15, bb = bk >> 4;
    const int lane = tid & 31, wid = tid >> 5;
    const int widx = wid*8 + (lane & 7);
    const int r_l = widx & 15, b_l = widx >> 4, q = lane >> 3;
    const int jl2 = tid & 7, b2 = tid >> 3;
    const int j = bk * 8 + jl2;
    const int mi = wid & 3, kq = wid >> 2;

    for (int i = tid; i < 16*1024; i += NTH) {
        int rl = i >> 10, d = i & 1023;
        su[rl*1028 + d] = u_h[(size_t)d*R + rb*16 + rl];
    }
    for (int i = tid; i < 32*96; i += NTH) {
        int row = i / 96, c8 = i - row*96;
        int wrow = (row >> 3) * H + bk * 8 + (row & 7);
        *reinterpret_cast<uint4*>(smc + OFF_W + row*WST + c8*16) =
            *reinterpret_cast<const uint4*>(g_Whp + (size_t)wrow*768 + c8*8);
    }

    float d2r[4], bhr[4];
    #pragma unroll
    for (int g = 0; g < 4; ++g) { d2r[g] = g_d2h[g*H + j]; bhr[g] = b_h[g*H + j]; }
    float hr = h0[b2*H + j];
    float cr = c0[b2*H + j];
    __syncthreads();

    unsigned bar = 0;
    for (int t = 0; t < T; ++t) {
        const float* gp = g_Gx + (size_t)t*(Bsz*G4H) + (size_t)b2*G4H + j;
        float gx0 = __ldcs(gp);
        float gx1 = __ldcs(gp + H);
        float gx2 = __ldcs(gp + 2*H);
        float gx3 = __ldcs(gp + 3*H);

        // ---- phase 1 (SIMT): p[8b,16r] = h[8b,:] @ u_h[:,16r] ----
        for (int i = tid; i < 8*256; i += NTH) {
            int row = i >> 8, c = i & 255;
            *reinterpret_cast<float4*>(&hst[row*1028 + c*4]) =
                __ldcg(reinterpret_cast<const float4*>(&g_h[(bb*8 + row)*H + c*4]));
        }
        __syncthreads();
        {
            unsigned long long a0 = 0ull, a1 = 0ull;
            const ulonglong2* hp = reinterpret_cast<const ulonglong2*>(&hst[b_l*1028 + q*256]);
            const ulonglong2* up = reinterpret_cast<const ulonglong2*>(&su[r_l*1028 + q*256]);
            #pragma unroll 8
            for (int k = 0; k < 64; ++k) {
                ulonglong2 hh = hp[k], uu = up[k];
                fma2(a0, hh.x, uu.x);
                fma2(a1, hh.y, uu.y);
            }
            float2 f0 = unpack2(a0), f1 = unpack2(a1);
            float s = (f0.x + f0.y) + (f1.x + f1.y);
            s += __shfl_xor_sync(0xffffffffu, s, 8);
            s += __shfl_xor_sync(0xffffffffu, s, 16);
            if ((lane & 31) < 8) {
                int b = bb*8 + b_l, r = rb*16 + r_l;
                __stcg(&g_pf[b*R + r], s);
            }
        }
        ++bar; gbar(bar);

        // ---- phase 2 (HMMA): stage p fp32 -> bf16 [hi|lo] in SMEM ----
        for (int i = tid; i < 64*64; i += NTH) {
            int row = i >> 6, c4 = i & 63;
            float4 v = __ldcg(reinterpret_cast<const float4*>(g_pf) + i);
            __nv_bfloat162 hA{__float2bfloat16(v.x), __float2bfloat16(v.y)};
            __nv_bfloat162 hB{__float2bfloat16(v.z), __float2bfloat16(v.w)};
            __nv_bfloat162 lA{__float2bfloat16(v.x-__bfloat162float(hA.x)),
                              __float2bfloat16(v.y-__bfloat162float(hA.y))};
            __nv_bfloat162 lB{__float2bfloat16(v.z-__bfloat162float(hB.x)),
                              __float2bfloat16(v.w-__bfloat162float(hB.y))};
            char* rp = smc + OFF_STG + row*AST + c4*8;
            *reinterpret_cast<__nv_bfloat162*>(rp)           = hA;
            *reinterpret_cast<__nv_bfloat162*>(rp + 4)       = hB;
            *reinterpret_cast<__nv_bfloat162*>(rp + 512)     = lA;
            *reinterpret_cast<__nv_bfloat162*>(rp + 516)     = lB;
        }
        __syncthreads();

        float acc[4][4];
        #pragma unroll
        for (int a = 0; a < 4; ++a)
            #pragma unroll
            for (int b = 0; b < 4; ++b) acc[a][b] = 0.f;
        #pragma unroll
        for (int k16 = 0; k16 < 12; ++k16) {
            const int kb = kq*384 + k16*32;
            const int aoff = kb & 1023;
            uint32_t afr[4];
            ldsm4(afr, SB + (mi*16 + (lane & 15))*AST + aoff + (lane >> 4)*16);
            uint32_t bfr[2][4];
            #pragma unroll
            for (int nb = 0; nb < 2; ++nb) {
                int sub = lane >> 3;
                int rn = nb*16 + (sub >> 1)*8 + (lane & 7);
                ldsm4(bfr[nb], WB + rn*WST + kb + (sub & 1)*16);
            }
            mma16816(acc[0], afr, bfr[0][0], bfr[0][1]);
            mma16816(acc[1], afr, bfr[0][2], bfr[0][3]);
            mma16816(acc[2], afr, bfr[1][0], bfr[1][1]);
            mma16816(acc[3], afr, bfr[1][2], bfr[1][3]);
        }
        __syncthreads();
        {
            const int quad = lane >> 2, tx2 = (lane & 3)*2;
            const int m0r = mi*16 + quad;
            #pragma unroll
            for (int n8 = 0; n8 < 4; ++n8) {
                int n = n8*8 + tx2;
                sp[kq*2112 + m0r*33 + n]       = acc[n8][0];
                sp[kq*2112 + m0r*33 + n + 1]   = acc[n8][1];
                sp[kq*2112 + (m0r+8)*33 + n]   = acc[n8][2];
                sp[kq*2112 + (m0r+8)*33 + n+1] = acc[n8][3];
            }
        }
        __syncthreads();

        float s0 = 0.f, s1 = 0.f, s2 = 0.f, s3 = 0.f;
        #pragma unroll
        for (int kk = 0; kk < 4; ++kk) {
            const float* bp = sp + kk*2112 + b2*33;
            s0 += bp[jl2]; s1 += bp[8 + jl2]; s2 += bp[16 + jl2]; s3 += bp[24 + jl2];
        }
        float pi = s0 + hr*d2r[0] + bhr[0] + gx0;
        float pf = s1 + hr*d2r[1] + bhr[1] + gx1;
        float po = s2 + hr*d2r[2] + bhr[2] + gx2;
        float pn = s3 + hr*d2r[3] + bhr[3] + gx3;

        float ig = 1.f/(1.f+expf(-pi));
        float fg = 1.f/(1.f+expf(-pf));
        float og = 1.f/(1.f+expf(-po));
        float ng = tanhf(pn);
        cr = fg*cr + ig*ng;
        hr = og*tanhf(cr);

        __stcg(&g_h[b2*H + j], hr);
        ++bar; gbar(bar);
        __stcs(&out[(size_t)t*(Bsz*H) + b2*H + j], hr);
        if (t == T-1 && full_out) {
            out[(size_t)T*Bsz*H + b2*H + j]          = hr;
            out[(size_t)T*Bsz*H + Bsz*H + b2*H + j]  = cr;
        }
    }
}

// ---------------------------------------------------------------------------
extern "C" void kernel_launch(void* const* d_in, const int* in_sizes, int n_in,
                              void* d_out, int out_size)
{
    const float* x     = (const float*)d_in[0];
    const float* h0    = (const float*)d_in[1];
    const float* c0    = (const float*)d_in[2];
    const float* u_x   = (const float*)d_in[3];
    const float* u_h   = (const float*)d_in[4];
    const float* w_x   = (const float*)d_in[5];
    const float* w_h   = (const float*)d_in[6];
    const float* b_x   = (const float*)d_in[7];
    const float* b_h   = (const float*)d_in[8];
    const float* dia_x = (const float*)d_in[9];
    const float* dia_h = (const float*)d_in[10];
    float* out = (float*)d_out;

    float *pGx=nullptr, *pd2x=nullptr;
    __nv_bfloat16 *pXp=nullptr, *pWp=nullptr, *pUp=nullptr, *pPp=nullptr, *pWhp=nullptr;
    cudaGetSymbolAddress((void**)&pGx,  g_Gx);
    cudaGetSymbolAddress((void**)&pd2x, g_d2x);
    cudaGetSymbolAddress((void**)&pXp,  g_Xp);
    cudaGetSymbolAddress((void**)&pWp,  g_Wp);
    cudaGetSymbolAddress((void**)&pUp,  g_Up);
    cudaGetSymbolAddress((void**)&pPp,  g_Pp);
    cudaGetSymbolAddress((void**)&pWhp, g_Whp);

    prep_kernel<<<32, 256>>>(u_x, w_x, dia_x, u_h, w_h, dia_h, h0);
    conv_pack<<<2048, 256>>>(x, pXp, 10, TB*D/4);
    conv_wB  <<<512,  256>>>(w_x, pWp);
    conv_wB  <<<512,  256>>>(w_h, pWhp);
    conv_uT  <<<256,  256>>>(u_x, pUp);

    cudaFuncSetAttribute(gemm_mma<1>, cudaFuncAttributeMaxDynamicSharedMemorySize, (int)GSM);
    cudaFuncSetAttribute(gemm_mma<2>, cudaFuncAttributeMaxDynamicSharedMemorySize, (int)GSM);

    {
        dim3 grid(R/128, TB/128);
        gemm_mma<1><<<grid, 256, GSM>>>(pXp, pUp, 3*D, 0,
                                        nullptr, pPp, nullptr, nullptr, nullptr);
    }
    {
        dim3 grid(G4H/128, TB/128);
        gemm_mma<2><<<grid, 256, GSM>>>(pPp, pWp, 3*R, G4H,
                                        pGx, nullptr, x, pd2x, b_x);
    }
    cudaFuncSetAttribute(lstm_rec, cudaFuncAttributeMaxDynamicSharedMemorySize, SMEM_REC);
    int full_out = (out_size >= T*Bsz*H + 2*Bsz*H) ? 1 : 0;
    lstm_rec<<<NB, NTH, SMEM_REC>>>(c0, h0, u_h, b_h, out, full_out);
}

// round 15
// speedup vs baseline: 1.1348x; 1.1348x over previous
#include <cuda_runtime.h>
#include <cuda_bf16.h>
#include <cstdint>
#include <cstddef>

constexpr int T=256, Bsz=64, D=1024, H=1024, R=256;
constexpr int G4H=4*H, TB=T*Bsz, NB=128, NTH=512;

// static scratch (allocation-free)
__device__ __align__(256) __nv_bfloat16 g_Xp[(size_t)TB*3*D];    // X'  [TB, 3072]
__device__ __align__(256) __nv_bfloat16 g_Wp[(size_t)G4H*3*R];   // Wx' [4096, 768]
__device__ __align__(256) __nv_bfloat16 g_Up[(size_t)R*3*D];     // UxT'[256, 3072]
__device__ __align__(256) __nv_bfloat16 g_Pp[(size_t)TB*3*R];    // P'  [TB, 768]
__device__ __align__(256) __nv_bfloat16 g_Whp[(size_t)G4H*3*R];  // Wh' [4096, 768]
__device__ __align__(256) float g_pf[Bsz*R];                     // p fp32 per step
__device__ float g_Gx[(size_t)TB*G4H];
__device__ float g_d2x[G4H];
__device__ float g_d2h[G4H];
__device__ float g_h[Bsz*H];
__device__ __align__(128) unsigned g_grp[8*8];                   // 8 group counters, 32B apart
__device__ __align__(128) unsigned g_epoch;

// ---------------- helpers ----------------
__device__ __forceinline__ void fma2(unsigned long long& acc,
                                     unsigned long long a, unsigned long long b) {
    asm("fma.rn.f32x2 %0, %1, %2, %0;" : "+l"(acc) : "l"(a), "l"(b));
}
__device__ __forceinline__ float2 unpack2(unsigned long long v) {
    float2 f; asm("mov.b64 {%0, %1}, %2;" : "=f"(f.x), "=f"(f.y) : "l"(v)); return f;
}
__device__ __forceinline__ uint32_t smem_u32(const void* p) {
    uint32_t a;
    asm("{ .reg .u64 t; cvta.to.shared.u64 t, %1; cvt.u32.u64 %0, t; }" : "=r"(a) : "l"(p));
    return a;
}
__device__ __forceinline__ void cp16(uint32_t dst, const void* src) {
    asm volatile("cp.async.cg.shared.global [%0], [%1], 16;" :: "r"(dst), "l"(src) : "memory");
}
__device__ __forceinline__ uint32_t swz(uint32_t o) { return o ^ ((o >> 3) & 0x70); }

__device__ __forceinline__ void ldsm4(uint32_t* r, uint32_t addr) {
    asm volatile("ldmatrix.sync.aligned.m8n8.x4.shared.b16 {%0,%1,%2,%3}, [%4];"
        : "=r"(r[0]), "=r"(r[1]), "=r"(r[2]), "=r"(r[3]) : "r"(addr));
}
__device__ __forceinline__ void mma16816(float* c, const uint32_t* a,
                                         uint32_t b0, uint32_t b1) {
    asm volatile(
        "mma.sync.aligned.m16n8k16.row.col.f32.bf16.bf16.f32 "
        "{%0,%1,%2,%3}, {%4,%5,%6,%7}, {%8,%9}, {%0,%1,%2,%3};"
        : "+f"(c[0]), "+f"(c[1]), "+f"(c[2]), "+f"(c[3])
        : "r"(a[0]), "r"(a[1]), "r"(a[2]), "r"(a[3]), "r"(b0), "r"(b1));
}

// ---------------- grid barrier: two-level (group counters + epoch) ----------
// Arrival: tid0 red.release to g_grp[bk&7] (16 arrivals/address, 8 addresses).
// Publish: CTA0 threads 0..7 acquire-poll group counters (parallel), bar.sync,
//          tid0 release-stores g_epoch = k.
// Detect:  each CTA's tid0 acquire-polls g_epoch (128 pollers, one address),
//          bar.sync fans HB to the whole CTA.
__device__ __forceinline__ void gbar(unsigned k) {
    const unsigned tgt16 = k * 16u;
    __syncthreads();
    if (threadIdx.x == 0)
        asm volatile("red.release.gpu.global.add.u32 [%0], 1;"
                     :: "l"(&g_grp[(blockIdx.x & 7) * 8]) : "memory");
    if (blockIdx.x == 0) {
        if (threadIdx.x < 8) {
            unsigned v;
            do {
                asm volatile("ld.acquire.gpu.global.u32 %0, [%1];"
                             : "=r"(v) : "l"(&g_grp[threadIdx.x * 8]) : "memory");
            } while (v < tgt16);
        }
        __syncthreads();
        if (threadIdx.x == 0)
            asm volatile("st.release.gpu.global.u32 [%0], %1;"
                         :: "l"(&g_epoch), "r"(k) : "memory");
    }
    if (threadIdx.x == 0) {
        unsigned v;
        do {
            asm volatile("ld.acquire.gpu.global.u32 %0, [%1];"
                         : "=r"(v) : "l"(&g_epoch) : "memory");
        } while (v < k);
    }
    __syncthreads();
}

// ---------------- conversions ----------------
__global__ void conv_pack(const float* __restrict__ s, __nv_bfloat16* __restrict__ d,
                          int ls, int n4)
{
    const int rl = 1 << ls, mask = rl - 1;
    for (int i = blockIdx.x*blockDim.x + threadIdx.x; i < n4; i += gridDim.x*blockDim.x) {
        float4 v = reinterpret_cast<const float4*>(s)[i];
        int e = i * 4, m = e >> ls, col = e & mask;
        __nv_bfloat16 h0=__float2bfloat16(v.x), h1=__float2bfloat16(v.y);
        __nv_bfloat16 h2=__float2bfloat16(v.z), h3=__float2bfloat16(v.w);
        __nv_bfloat162 ha{h0,h1}, hb{h2,h3};
        __nv_bfloat162 la{__float2bfloat16(v.x-__bfloat162float(h0)),
                          __float2bfloat16(v.y-__bfloat162float(h1))};
        __nv_bfloat162 lb{__float2bfloat16(v.z-__bfloat162float(h2)),
                          __float2bfloat16(v.w-__bfloat162float(h3))};
        __nv_bfloat16* rp = d + (size_t)m*3*rl + col;
        reinterpret_cast<__nv_bfloat162*>(rp)[0]        = ha;
        reinterpret_cast<__nv_bfloat162*>(rp)[1]        = hb;
        reinterpret_cast<__nv_bfloat162*>(rp + rl)[0]   = la;
        reinterpret_cast<__nv_bfloat162*>(rp + rl)[1]   = lb;
        reinterpret_cast<__nv_bfloat162*>(rp + 2*rl)[0] = ha;
        reinterpret_cast<__nv_bfloat162*>(rp + 2*rl)[1] = hb;
    }
}
__global__ void conv_uT(const float* __restrict__ u, __nv_bfloat16* __restrict__ d)
{
    for (int i = blockIdx.x*blockDim.x + threadIdx.x; i < R*D; i += gridDim.x*blockDim.x) {
        int n = i >> 10, dd = i & 1023;
        float v = u[(size_t)dd*R + n];
        __nv_bfloat16 h = __float2bfloat16(v);
        __nv_bfloat16 l = __float2bfloat16(v - __bfloat162float(h));
        d[(size_t)n*3*D + dd]       = h;
        d[(size_t)n*3*D + D + dd]   = h;
        d[(size_t)n*3*D + 2*D + dd] = l;
    }
}
// rows of 256 fp32 -> rows of 768 bf16 [hi | hi | lo]
__global__ void conv_wB(const float* __restrict__ w, __nv_bfloat16* __restrict__ d)
{
    for (int i = blockIdx.x*blockDim.x + threadIdx.x; i < G4H*R/4; i += gridDim.x*blockDim.x) {
        float4 v = reinterpret_cast<const float4*>(w)[i];
        int e = i * 4, m = e >> 8, col = e & 255;
        __nv_bfloat16 h0=__float2bfloat16(v.x), h1=__float2bfloat16(v.y);
        __nv_bfloat16 h2=__float2bfloat16(v.z), h3=__float2bfloat16(v.w);
        __nv_bfloat162 ha{h0,h1}, hb{h2,h3};
        __nv_bfloat162 la{__float2bfloat16(v.x-__bfloat162float(h0)),
                          __float2bfloat16(v.y-__bfloat162float(h1))};
        __nv_bfloat162 lb{__float2bfloat16(v.z-__bfloat162float(h2)),
                          __float2bfloat16(v.w-__bfloat162float(h3))};
        __nv_bfloat16* rp = d + (size_t)m*3*R + col;
        reinterpret_cast<__nv_bfloat162*>(rp)[0]         = ha;
        reinterpret_cast<__nv_bfloat162*>(rp)[1]         = hb;
        reinterpret_cast<__nv_bfloat162*>(rp + R)[0]     = ha;
        reinterpret_cast<__nv_bfloat162*>(rp + R)[1]     = hb;
        reinterpret_cast<__nv_bfloat162*>(rp + 2*R)[0]   = la;
        reinterpret_cast<__nv_bfloat162*>(rp + 2*R)[1]   = lb;
    }
}

// ---------------- prep ----------------
__global__ void prep_kernel(const float* __restrict__ u_x, const float* __restrict__ w_x,
                            const float* __restrict__ dia_x,
                            const float* __restrict__ u_h, const float* __restrict__ w_h,
                            const float* __restrict__ dia_h, const float* __restrict__ h0)
{
    int n = blockIdx.x*blockDim.x + threadIdx.x;   // 0..8191
    if (n < 8*8) g_grp[n] = 0u;                    // barrier reset (replay-safe)
    if (n == 64) g_epoch = 0u;
    const float *u, *w, *dia; float* o; int idx;
    if (n < G4H) { u=u_x; w=w_x; dia=dia_x; o=g_d2x; idx=n; }
    else         { u=u_h; w=w_h; dia=dia_h; o=g_d2h; idx=n-G4H; }
    int d = idx & (H-1);
    const float4* ur = reinterpret_cast<const float4*>(u + (size_t)d*R);
    const float4* wr = reinterpret_cast<const float4*>(w + (size_t)idx*R);
    float s = 0.f;
    #pragma unroll 8
    for (int k = 0; k < R/4; ++k) {
        float4 a = ur[k], b = wr[k];
        s += a.x*b.x + a.y*b.y + a.z*b.z + a.w*b.w;
    }
    o[idx] = dia[d] - s;
    for (int i = n; i < Bsz*H; i += 8192) g_h[i] = h0[i];
}

// ---------------------------------------------------------------------------
// HMMA GEMM for precompute (unchanged)
// ---------------------------------------------------------------------------
constexpr size_t GSM = 2*32768 + 1024;

template<int EPI>
__global__ void __launch_bounds__(256, 1) gemm_mma(
    const __nv_bfloat16* __restrict__ Ap, const __nv_bfloat16* __restrict__ Bp,
    int K, int Nld, float* __restrict__ Cf, __nv_bfloat16* __restrict__ Pp,
    const float* __restrict__ X, const float* __restrict__ d2v,
    const float* __restrict__ bias)
{
    extern __shared__ char smraw[];
    const uint32_t sb = (smem_u32(smraw) + 1023) & ~1023u;
    const int tid = threadIdx.x, lane = tid & 31, wid = tid >> 5;
    const int wm = wid >> 2, wn = wid & 3;
    const int m0 = blockIdx.y * 128, n0 = blockIdx.x * 128;

    const __nv_bfloat16* Asrc = Ap + (size_t)m0 * K;
    const __nv_bfloat16* Bsrc = Bp + (size_t)n0 * K;
    const int lrow = tid >> 3, lc8 = tid & 7;

    auto load_stage = [&](int kc, int s) {
        uint32_t base = sb + s * 32768;
        #pragma unroll
        for (int rr = 0; rr < 4; ++rr) {
            int row = lrow + rr * 32;
            cp16(base + swz(row*128 + lc8*16),
                 Asrc + (size_t)row*K + kc + lc8*8);
            cp16(base + 16384 + swz(row*128 + lc8*16),
                 Bsrc + (size_t)row*K + kc + lc8*8);
        }
        asm volatile("cp.async.commit_group;" ::: "memory");
    };

    float acc[4][4][4];
    #pragma unroll
    for (int a = 0; a < 4; ++a)
        #pragma unroll
        for (int b = 0; b < 4; ++b)
            #pragma unroll
            for (int c = 0; c < 4; ++c) acc[a][b][c] = 0.f;

    const int nIter = K / 64;
    load_stage(0, 0);
    for (int it = 0; it < nIter; ++it) {
        if (it + 1 < nIter) {
            load_stage((it + 1) * 64, (it + 1) & 1);
            asm volatile("cp.async.wait_group 1;" ::: "memory");
        } else {
            asm volatile("cp.async.wait_group 0;" ::: "memory");
        }
        __syncthreads();
        const uint32_t aB = sb + (it & 1) * 32768;
        const uint32_t bB = aB + 16384;
        #pragma unroll
        for (int kk = 0; kk < 4; ++kk) {
            uint32_t afr[4][4];
            #pragma unroll
            for (int mi = 0; mi < 4; ++mi) {
                int rowa = wm*64 + mi*16 + (lane & 15);
                ldsm4(afr[mi], aB + swz(rowa*128 + kk*32 + (lane >> 4)*16));
            }
            uint32_t bfr[2][4];
            #pragma unroll
            for (int nb = 0; nb < 2; ++nb) {
                int sub = lane >> 3;
                int rn = wn*32 + nb*16 + (sub >> 1)*8 + (lane & 7);
                ldsm4(bfr[nb], bB + swz(rn*128 + kk*32 + (sub & 1)*16));
            }
            #pragma unroll
            for (int mi = 0; mi < 4; ++mi)
                #pragma unroll
                for (int nb = 0; nb < 2; ++nb) {
                    mma16816(acc[mi][nb*2],     afr[mi], bfr[nb][0], bfr[nb][1]);
                    mma16816(acc[mi][nb*2 + 1], afr[mi], bfr[nb][2], bfr[nb][3]);
                }
        }
        __syncthreads();
    }

    const int quad = lane >> 2, tx2 = (lane & 3) * 2;
    #pragma unroll
    for (int mi = 0; mi < 4; ++mi) {
        #pragma unroll
        for (int n8 = 0; n8 < 4; ++n8) {
            int n = n0 + wn*32 + n8*8 + tx2;
            #pragma unroll
            for (int half = 0; half < 2; ++half) {
                int m = m0 + wm*64 + mi*16 + quad + half*8;
                float v0 = acc[mi][n8][half*2], v1 = acc[mi][n8][half*2 + 1];
                if constexpr (EPI == 2) {
                    float x0 = X[(size_t)m*H + (n & (H-1))];
                    float x1 = X[(size_t)m*H + ((n+1) & (H-1))];
                    v0 += x0*d2v[n]   + bias[n];
                    v1 += x1*d2v[n+1] + bias[n+1];
                    *reinterpret_cast<float2*>(&Cf[(size_t)m*Nld + n]) =
                        make_float2(v0, v1);
                } else {
                    __nv_bfloat16 h0 = __float2bfloat16(v0);
                    __nv_bfloat16 h1 = __float2bfloat16(v1);
                    __nv_bfloat162 hh{h0, h1};
                    __nv_bfloat162 ll{__float2bfloat16(v0 - __bfloat162float(h0)),
                                      __float2bfloat16(v1 - __bfloat162float(h1))};
                    __nv_bfloat16* rp = Pp + (size_t)m*(3*R) + n;
                    *reinterpret_cast<__nv_bfloat162*>(rp)         = hh;
                    *reinterpret_cast<__nv_bfloat162*>(rp + R)     = ll;
                    *reinterpret_cast<__nv_bfloat162*>(rp + 2*R)   = hh;
                }
            }
        }
    }
}

// ---------------------------------------------------------------------------
// persistent recurrent kernel (identical to R13 except gbar)
// ---------------------------------------------------------------------------
constexpr int OFF_W   = 65792;
constexpr int OFF_STG = 115456;
constexpr int SMEM_REC = 182016;
constexpr int WST  = 1552;
constexpr int AST  = 1040;

__global__ void __launch_bounds__(NTH, 1) lstm_rec(
    const float* __restrict__ c0, const float* __restrict__ h0,
    const float* __restrict__ u_h,
    const float* __restrict__ b_h, float* __restrict__ out, int full_out)
{
    extern __shared__ char smc[];
    float* su  = reinterpret_cast<float*>(smc);
    float* hst = reinterpret_cast<float*>(smc + OFF_STG);
    float* sp  = reinterpret_cast<float*>(smc + OFF_STG);
    const uint32_t sb = smem_u32(smc);
    const uint32_t WB = sb + OFF_W, SB = sb + OFF_STG;

    const int tid = threadIdx.x, bk = blockIdx.x;
    const int rb = bk & 15, bb = bk >> 4;
    const int lane = tid & 31, wid = tid >> 5;
    const int widx = wid*8 + (lane & 7);
    const int r_l = widx & 15, b_l = widx >> 4, q = lane >> 3;
    const int jl2 = tid & 7, b2 = tid >> 3;
    const int j = bk * 8 + jl2;
    const int mi = wid & 3, kq = wid >> 2;

    for (int i = tid; i < 16*1024; i += NTH) {
        int rl = i >> 10, d = i & 1023;
        su[rl*1028 + d] = u_h[(size_t)d*R + rb*16 + rl];
    }
    for (int i = tid; i < 32*96; i += NTH) {
        int row = i / 96, c8 = i - row*96;
        int wrow = (row >> 3) * H + bk * 8 + (row & 7);
        *reinterpret_cast<uint4*>(smc + OFF_W + row*WST + c8*16) =
            *reinterpret_cast<const uint4*>(g_Whp + (size_t)wrow*768 + c8*8);
    }

    float d2r[4], bhr[4];
    #pragma unroll
    for (int g = 0; g < 4; ++g) { d2r[g] = g_d2h[g*H + j]; bhr[g] = b_h[g*H + j]; }
    float hr = h0[b2*H + j];
    float cr = c0[b2*H + j];
    __syncthreads();

    unsigned bar = 0;
    for (int t = 0; t < T; ++t) {
        const float* gp = g_Gx + (size_t)t*(Bsz*G4H) + (size_t)b2*G4H + j;
        float gx0 = __ldcs(gp);
        float gx1 = __ldcs(gp + H);
        float gx2 = __ldcs(gp + 2*H);
        float gx3 = __ldcs(gp + 3*H);

        // ---- phase 1 (SIMT): p[8b,16r] = h[8b,:] @ u_h[:,16r] ----
        for (int i = tid; i < 8*256; i += NTH) {
            int row = i >> 8, c = i & 255;
            *reinterpret_cast<float4*>(&hst[row*1028 + c*4]) =
                __ldcg(reinterpret_cast<const float4*>(&g_h[(bb*8 + row)*H + c*4]));
        }
        __syncthreads();
        {
            unsigned long long a0 = 0ull, a1 = 0ull;
            const ulonglong2* hp = reinterpret_cast<const ulonglong2*>(&hst[b_l*1028 + q*256]);
            const ulonglong2* up = reinterpret_cast<const ulonglong2*>(&su[r_l*1028 + q*256]);
            #pragma unroll 8
            for (int k = 0; k < 64; ++k) {
                ulonglong2 hh = hp[k], uu = up[k];
                fma2(a0, hh.x, uu.x);
                fma2(a1, hh.y, uu.y);
            }
            float2 f0 = unpack2(a0), f1 = unpack2(a1);
            float s = (f0.x + f0.y) + (f1.x + f1.y);
            s += __shfl_xor_sync(0xffffffffu, s, 8);
            s += __shfl_xor_sync(0xffffffffu, s, 16);
            if ((lane & 31) < 8) {
                int b = bb*8 + b_l, r = rb*16 + r_l;
                __stcg(&g_pf[b*R + r], s);
            }
        }
        ++bar; gbar(bar);

        // ---- phase 2 (HMMA): stage p fp32 -> bf16 [hi|lo] in SMEM ----
        for (int i = tid; i < 64*64; i += NTH) {
            int row = i >> 6, c4 = i & 63;
            float4 v = __ldcg(reinterpret_cast<const float4*>(g_pf) + i);
            __nv_bfloat162 hA{__float2bfloat16(v.x), __float2bfloat16(v.y)};
            __nv_bfloat162 hB{__float2bfloat16(v.z), __float2bfloat16(v.w)};
            __nv_bfloat162 lA{__float2bfloat16(v.x-__bfloat162float(hA.x)),
                              __float2bfloat16(v.y-__bfloat162float(hA.y))};
            __nv_bfloat162 lB{__float2bfloat16(v.z-__bfloat162float(hB.x)),
                              __float2bfloat16(v.w-__bfloat162float(hB.y))};
            char* rp = smc + OFF_STG + row*AST + c4*8;
            *reinterpret_cast<__nv_bfloat162*>(rp)           = hA;
            *reinterpret_cast<__nv_bfloat162*>(rp + 4)       = hB;
            *reinterpret_cast<__nv_bfloat162*>(rp + 512)     = lA;
            *reinterpret_cast<__nv_bfloat162*>(rp + 516)     = lB;
        }
        __syncthreads();

        float acc[4][4];
        #pragma unroll
        for (int a = 0; a < 4; ++a)
            #pragma unroll
            for (int b = 0; b < 4; ++b) acc[a][b] = 0.f;
        #pragma unroll
        for (int k16 = 0; k16 < 12; ++k16) {
            const int kb = kq*384 + k16*32;
            const int aoff = kb & 1023;
            uint32_t afr[4];
            ldsm4(afr, SB + (mi*16 + (lane & 15))*AST + aoff + (lane >> 4)*16);
            uint32_t bfr[2][4];
            #pragma unroll
            for (int nb = 0; nb < 2; ++nb) {
                int sub = lane >> 3;
                int rn = nb*16 + (sub >> 1)*8 + (lane & 7);
                ldsm4(bfr[nb], WB + rn*WST + kb + (sub & 1)*16);
            }
            mma16816(acc[0], afr, bfr[0][0], bfr[0][1]);
            mma16816(acc[1], afr, bfr[0][2], bfr[0][3]);
            mma16816(acc[2], afr, bfr[1][0], bfr[1][1]);
            mma16816(acc[3], afr, bfr[1][2], bfr[1][3]);
        }
        __syncthreads();
        {
            const int quad = lane >> 2, tx2 = (lane & 3)*2;
            const int m0r = mi*16 + quad;
            #pragma unroll
            for (int n8 = 0; n8 < 4; ++n8) {
                int n = n8*8 + tx2;
                sp[kq*2112 + m0r*33 + n]       = acc[n8][0];
                sp[kq*2112 + m0r*33 + n + 1]   = acc[n8][1];
                sp[kq*2112 + (m0r+8)*33 + n]   = acc[n8][2];
                sp[kq*2112 + (m0r+8)*33 + n+1] = acc[n8][3];
            }
        }
        __syncthreads();

        float s0 = 0.f, s1 = 0.f, s2 = 0.f, s3 = 0.f;
        #pragma unroll
        for (int kk = 0; kk < 4; ++kk) {
            const float* bp = sp + kk*2112 + b2*33;
            s0 += bp[jl2]; s1 += bp[8 + jl2]; s2 += bp[16 + jl2]; s3 += bp[24 + jl2];
        }
        float pi = s0 + hr*d2r[0] + bhr[0] + gx0;
        float pf = s1 + hr*d2r[1] + bhr[1] + gx1;
        float po = s2 + hr*d2r[2] + bhr[2] + gx2;
        float pn = s3 + hr*d2r[3] + bhr[3] + gx3;

        float ig = 1.f/(1.f+expf(-pi));
        float fg = 1.f/(1.f+expf(-pf));
        float og = 1.f/(1.f+expf(-po));
        float ng = tanhf(pn);
        cr = fg*cr + ig*ng;
        hr = og*tanhf(cr);

        __stcg(&g_h[b2*H + j], hr);
        ++bar; gbar(bar);
        __stcs(&out[(size_t)t*(Bsz*H) + b2*H + j], hr);
        if (t == T-1 && full_out) {
            out[(size_t)T*Bsz*H + b2*H + j]          = hr;
            out[(size_t)T*Bsz*H + Bsz*H + b2*H + j]  = cr;
        }
    }
}

// ---------------------------------------------------------------------------
extern "C" void kernel_launch(void* const* d_in, const int* in_sizes, int n_in,
                              void* d_out, int out_size)
{
    const float* x     = (const float*)d_in[0];
    const float* h0    = (const float*)d_in[1];
    const float* c0    = (const float*)d_in[2];
    const float* u_x   = (const float*)d_in[3];
    const float* u_h   = (const float*)d_in[4];
    const float* w_x   = (const float*)d_in[5];
    const float* w_h   = (const float*)d_in[6];
    const float* b_x   = (const float*)d_in[7];
    const float* b_h   = (const float*)d_in[8];
    const float* dia_x = (const float*)d_in[9];
    const float* dia_h = (const float*)d_in[10];
    float* out = (float*)d_out;

    float *pGx=nullptr, *pd2x=nullptr;
    __nv_bfloat16 *pXp=nullptr, *pWp=nullptr, *pUp=nullptr, *pPp=nullptr, *pWhp=nullptr;
    cudaGetSymbolAddress((void**)&pGx,  g_Gx);
    cudaGetSymbolAddress((void**)&pd2x, g_d2x);
    cudaGetSymbolAddress((void**)&pXp,  g_Xp);
    cudaGetSymbolAddress((void**)&pWp,  g_Wp);
    cudaGetSymbolAddress((void**)&pUp,  g_Up);
    cudaGetSymbolAddress((void**)&pPp,  g_Pp);
    cudaGetSymbolAddress((void**)&pWhp, g_Whp);

    prep_kernel<<<32, 256>>>(u_x, w_x, dia_x, u_h, w_h, dia_h, h0);
    conv_pack<<<2048, 256>>>(x, pXp, 10, TB*D/4);
    conv_wB  <<<512,  256>>>(w_x, pWp);
    conv_wB  <<<512,  256>>>(w_h, pWhp);
    conv_uT  <<<256,  256>>>(u_x, pUp);

    cudaFuncSetAttribute(gemm_mma<1>, cudaFuncAttributeMaxDynamicSharedMemorySize, (int)GSM);
    cudaFuncSetAttribute(gemm_mma<2>, cudaFuncAttributeMaxDynamicSharedMemorySize, (int)GSM);

    {
        dim3 grid(R/128, TB/128);
        gemm_mma<1><<<grid, 256, GSM>>>(pXp, pUp, 3*D, 0,
                                        nullptr, pPp, nullptr, nullptr, nullptr);
    }
    {
        dim3 grid(G4H/128, TB/128);
        gemm_mma<2><<<grid, 256, GSM>>>(pPp, pWp, 3*R, G4H,
                                        pGx, nullptr, x, pd2x, b_x);
    }
    cudaFuncSetAttribute(lstm_rec, cudaFuncAttributeMaxDynamicSharedMemorySize, SMEM_REC);
    int full_out = (out_size >= T*Bsz*H + 2*Bsz*H) ? 1 : 0;
    lstm_rec<<<NB, NTH, SMEM_REC>>>(c0, h0, u_h, b_h, out, full_out);
}